// round 1
// baseline (speedup 1.0000x reference)
#include <cuda_runtime.h>
#include <math.h>

#define B_ 4
#define T_ 2048
#define EMB_ 2048
#define HD_ 128
#define HALF_ 64
#define SCALE_ 0.08838834764831845f   // 1/sqrt(128)

// Scratch for projected Q/K/V (allocation-free rule: __device__ globals)
__device__ float g_Q[B_ * T_ * HD_];
__device__ float g_K[B_ * T_ * HD_];
__device__ float g_V[B_ * T_ * HD_];

// ---------------------------------------------------------------------------
// Kernel A: QKV projection + RoPE.
// grid (64, 3): 64 M-tiles of 128 rows, y selects {Q,K,V}. Block 256 threads.
// Tile: 128(M) x 128(N=HD), K-chunks of 32. Classic SGEMM register tiling 8x8.
// RoPE applied in the epilogue for Q and K.
// ---------------------------------------------------------------------------
__global__ __launch_bounds__(256) void qkv_kernel(
    const float* __restrict__ x,  const float* __restrict__ Wq,
    const float* __restrict__ Wk, const float* __restrict__ Wv,
    const float* __restrict__ rc, const float* __restrict__ rs)
{
    __shared__ float As[32][129];   // [k][m], pad 129 -> conflict-light transpose
    __shared__ float Bs[32][128];   // [k][n]

    const int m0    = blockIdx.x * 128;
    const int which = blockIdx.y;
    const float* W  = (which == 0) ? Wq : (which == 1) ? Wk : Wv;
    float* out      = (which == 0) ? g_Q : (which == 1) ? g_K : g_V;

    const int tid = threadIdx.x;
    const int tx  = tid & 15;       // 16 col-groups
    const int ty  = tid >> 4;       // 16 row-groups
    const int r0  = ty * 8;

    float acc[8][8];
#pragma unroll
    for (int i = 0; i < 8; i++)
#pragma unroll
        for (int j = 0; j < 8; j++) acc[i][j] = 0.f;

    for (int k0 = 0; k0 < EMB_; k0 += 32) {
        // load x tile 128x32 -> As[k][m] (transposed)
#pragma unroll
        for (int it = 0; it < 4; it++) {
            int idx = it * 256 + tid;
            int r   = idx >> 3;             // 0..127
            int kk  = (idx & 7) << 2;       // 0..28
            float4 v = *(const float4*)(x + (size_t)(m0 + r) * EMB_ + k0 + kk);
            As[kk + 0][r] = v.x; As[kk + 1][r] = v.y;
            As[kk + 2][r] = v.z; As[kk + 3][r] = v.w;
        }
        // load W tile 32x128 -> Bs[k][n]
#pragma unroll
        for (int it = 0; it < 4; it++) {
            int idx = it * 256 + tid;
            int kk  = idx >> 5;             // 0..31
            int n   = (idx & 31) << 2;      // 0..124
            *(float4*)&Bs[kk][n] = *(const float4*)(W + (size_t)(k0 + kk) * HD_ + n);
        }
        __syncthreads();

#pragma unroll
        for (int kk = 0; kk < 32; kk++) {
            float a[8];
#pragma unroll
            for (int i = 0; i < 8; i++) a[i] = As[kk][r0 + i];
            float4 b0 = *(float4*)&Bs[kk][tx * 4];        // cols tx*4..+3
            float4 b1 = *(float4*)&Bs[kk][64 + tx * 4];   // cols 64+tx*4..+3
            float b[8] = {b0.x, b0.y, b0.z, b0.w, b1.x, b1.y, b1.z, b1.w};
#pragma unroll
            for (int i = 0; i < 8; i++)
#pragma unroll
                for (int j = 0; j < 8; j++) acc[i][j] += a[i] * b[j];
        }
        __syncthreads();
    }

    // Epilogue: RoPE for Q/K, plain store for V. Cols: tx*4 and 64+tx*4.
#pragma unroll
    for (int i = 0; i < 8; i++) {
        int rg = m0 + r0 + i;
        int t  = rg & (T_ - 1);
        float o[8];
        if (which < 2) {
#pragma unroll
            for (int h = 0; h < 2; h++) {           // two float4 halves
                int cbase = (h == 0) ? (tx * 4) : (64 + tx * 4);
#pragma unroll
                for (int p = 0; p < 2; p++) {       // two rope pairs per float4
                    int col = cbase + 2 * p;
                    float co = rc[t * HALF_ + (col >> 1)];
                    float si = rs[t * HALF_ + (col >> 1)];
                    float re = acc[i][4 * h + 2 * p];
                    float im = acc[i][4 * h + 2 * p + 1];
                    o[4 * h + 2 * p]     = re * co - im * si;
                    o[4 * h + 2 * p + 1] = re * si + im * co;
                }
            }
        } else {
#pragma unroll
            for (int j = 0; j < 8; j++) o[j] = acc[i][j];
        }
        float* dst = out + (size_t)rg * HD_;
        *(float4*)(dst + tx * 4)      = make_float4(o[0], o[1], o[2], o[3]);
        *(float4*)(dst + 64 + tx * 4) = make_float4(o[4], o[5], o[6], o[7]);
    }
}

// ---------------------------------------------------------------------------
// Kernel B: causal flash attention, fp32.
// grid (32, 4): x = q-tile (64 rows), y = batch. Block 256 threads.
// Q and K held in smem as float4 chunks with XOR-8 swizzle (conflict-free
// column-of-rows reads). Online softmax, P in smem, PV accumulated in regs.
// Causality replaces the additive mask input exactly (exp underflows to 0).
// ---------------------------------------------------------------------------
#define FM 64
#define FN 64

__global__ __launch_bounds__(256) void attn_kernel(float* __restrict__ out)
{
    extern __shared__ float sm[];
    float4* Qs = (float4*)sm;          // [64][32] chunks, swizzle key (row&7)
    float4* Ks = Qs + 64 * 32;         // [64][32] chunks, swizzle key ((row>>2)&7)
    float4* Vs = Ks + 64 * 32;         // [64][32] chunks, plain
    float*  Ps = (float*)(Vs + 64 * 32);  // [64][65]
    float*  red = Ps + 64 * 65;           // [64] alpha / 1/l broadcast

    const int tid = threadIdx.x;
    const int tx  = tid & 15;
    const int ty  = tid >> 4;
    const int qt  = blockIdx.x;
    const int b   = blockIdx.y;
    const int q0  = qt * FM;

    const float* gQ = g_Q + (size_t)b * T_ * HD_;
    const float* gK = g_K + (size_t)b * T_ * HD_;
    const float* gV = g_V + (size_t)b * T_ * HD_;

    // Load Q tile (scaled by 1/sqrt(HD)), swizzled
#pragma unroll
    for (int it = 0; it < 8; it++) {
        int idx = it * 256 + tid;
        int r   = idx >> 5;            // 0..63
        int c   = (idx & 31) << 2;     // 0..124
        float4 v = *(const float4*)(gQ + (size_t)(q0 + r) * HD_ + c);
        v.x *= SCALE_; v.y *= SCALE_; v.z *= SCALE_; v.w *= SCALE_;
        Qs[r * 32 + ((c >> 2) ^ (r & 7))] = v;
    }

    float m_i = -1e30f, l_i = 0.f;     // live in threads tid<64 (row = tid)
    float o[4][8];
#pragma unroll
    for (int i = 0; i < 4; i++)
#pragma unroll
        for (int j = 0; j < 8; j++) o[i][j] = 0.f;

    const int nkv = q0 + FM;
    for (int j0 = 0; j0 < nkv; j0 += FN) {
        // Load K (swizzled) and V (plain) tiles
#pragma unroll
        for (int it = 0; it < 8; it++) {
            int idx = it * 256 + tid;
            int r   = idx >> 5;
            int c   = (idx & 31) << 2;
            float4 kv4 = *(const float4*)(gK + (size_t)(j0 + r) * HD_ + c);
            Ks[r * 32 + ((c >> 2) ^ ((r >> 2) & 7))] = kv4;
            float4 vv4 = *(const float4*)(gV + (size_t)(j0 + r) * HD_ + c);
            Vs[r * 32 + (c >> 2)] = vv4;
        }
        __syncthreads();

        // S = Q K^T (scale pre-folded). Micro tile 4x4 per thread.
        float s[4][4];
#pragma unroll
        for (int i = 0; i < 4; i++)
#pragma unroll
            for (int c = 0; c < 4; c++) s[i][c] = 0.f;

#pragma unroll 4
        for (int q4 = 0; q4 < 32; q4++) {
            float4 a[4], bb[4];
#pragma unroll
            for (int i = 0; i < 4; i++) {
                int row = ty * 4 + i;
                a[i] = Qs[row * 32 + (q4 ^ (row & 7))];
            }
#pragma unroll
            for (int c = 0; c < 4; c++) {
                int col = tx * 4 + c;
                bb[c] = Ks[col * 32 + (q4 ^ (tx & 7))];
            }
#pragma unroll
            for (int i = 0; i < 4; i++)
#pragma unroll
                for (int c = 0; c < 4; c++) {
                    s[i][c] += a[i].x * bb[c].x;
                    s[i][c] += a[i].y * bb[c].y;
                    s[i][c] += a[i].z * bb[c].z;
                    s[i][c] += a[i].w * bb[c].w;
                }
        }

        // Write S to Ps with causal mask (only the diagonal tile needs it)
        const bool diag = (j0 + FN > q0);
#pragma unroll
        for (int i = 0; i < 4; i++)
#pragma unroll
            for (int c = 0; c < 4; c++) {
                int row = ty * 4 + i, col = tx * 4 + c;
                float v = s[i][c];
                if (diag && (j0 + col > q0 + row)) v = -1e30f;
                Ps[row * 65 + col] = v;
            }
        __syncthreads();

        // Online softmax: one thread per row
        if (tid < 64) {
            float mx = m_i;
#pragma unroll 8
            for (int k = 0; k < FN; k++) mx = fmaxf(mx, Ps[tid * 65 + k]);
            float al = __expf(m_i - mx);
            float l  = l_i * al;
#pragma unroll 8
            for (int k = 0; k < FN; k++) {
                float p = __expf(Ps[tid * 65 + k] - mx);
                Ps[tid * 65 + k] = p;
                l += p;
            }
            m_i = mx; l_i = l;
            red[tid] = al;
        }
        __syncthreads();

        // Rescale O, then O += P @ V
        float al[4];
#pragma unroll
        for (int i = 0; i < 4; i++) al[i] = red[ty * 4 + i];
#pragma unroll
        for (int i = 0; i < 4; i++)
#pragma unroll
            for (int j = 0; j < 8; j++) o[i][j] *= al[i];

#pragma unroll 4
        for (int kk = 0; kk < FN; kk++) {
            float4 b0 = Vs[kk * 32 + tx];         // cols tx*4..+3
            float4 b1 = Vs[kk * 32 + 16 + tx];    // cols 64+tx*4..+3
#pragma unroll
            for (int i = 0; i < 4; i++) {
                float a = Ps[(ty * 4 + i) * 65 + kk];
                o[i][0] += a * b0.x; o[i][1] += a * b0.y;
                o[i][2] += a * b0.z; o[i][3] += a * b0.w;
                o[i][4] += a * b1.x; o[i][5] += a * b1.y;
                o[i][6] += a * b1.z; o[i][7] += a * b1.w;
            }
        }
        __syncthreads();
    }

    // Finalize: divide by l, store
    if (tid < 64) red[tid] = 1.f / l_i;
    __syncthreads();
#pragma unroll
    for (int i = 0; i < 4; i++) {
        float inv = red[ty * 4 + i];
        int row   = q0 + ty * 4 + i;
        float* dst = out + (size_t)(b * T_ + row) * HD_;
        *(float4*)(dst + tx * 4) =
            make_float4(o[i][0] * inv, o[i][1] * inv, o[i][2] * inv, o[i][3] * inv);
        *(float4*)(dst + 64 + tx * 4) =
            make_float4(o[i][4] * inv, o[i][5] * inv, o[i][6] * inv, o[i][7] * inv);
    }
}

// ---------------------------------------------------------------------------
extern "C" void kernel_launch(void* const* d_in, const int* in_sizes, int n_in,
                              void* d_out, int out_size) {
    const float* x  = (const float*)d_in[0];
    const float* Wq = (const float*)d_in[1];
    const float* Wk = (const float*)d_in[2];
    const float* Wv = (const float*)d_in[3];
    const float* rc = (const float*)d_in[4];
    const float* rs = (const float*)d_in[5];
    // d_in[6] = mask: unused — causality applied analytically (identical result)
    float* out = (float*)d_out;

    const int smem_attn = (3 * 64 * 32 * 4 + 64 * 65 + 64) * (int)sizeof(float); // 115456 B
    cudaFuncSetAttribute(attn_kernel,
                         cudaFuncAttributeMaxDynamicSharedMemorySize, smem_attn);

    qkv_kernel<<<dim3(64, 3), 256>>>(x, Wq, Wk, Wv, rc, rs);
    attn_kernel<<<dim3(32, B_), 256, smem_attn>>>(out);
}

// round 8
// speedup vs baseline: 1.7324x; 1.7324x over previous
#include <cuda_runtime.h>
#include <cstdint>
#include <math.h>

#define B_ 4
#define T_ 2048
#define EMB_ 2048
#define HD_ 128
#define HALF_ 64
#define SCALE_ 0.08838834764831845f   // 1/sqrt(128)

// __device__ scratch (allocation-free rule)
__device__ float g_Q[B_ * T_ * HD_];
__device__ float g_K[B_ * T_ * HD_];
__device__ float g_V[B_ * T_ * HD_];

__device__ __forceinline__ uint32_t to_tf32_bits(float v) {
    uint32_t r;
    asm("{ .reg .b32 t; cvt.rna.tf32.f32 t, %1; mov.b32 %0, t; }" : "=r"(r) : "f"(v));
    return r;
}

__device__ __forceinline__ void mma_tf32(float* c, const uint32_t* a, const uint32_t* b) {
    asm volatile(
        "mma.sync.aligned.m16n8k8.row.col.f32.tf32.tf32.f32 "
        "{%0,%1,%2,%3}, {%4,%5,%6,%7}, {%8,%9}, {%0,%1,%2,%3};"
        : "+f"(c[0]), "+f"(c[1]), "+f"(c[2]), "+f"(c[3])
        : "r"(a[0]), "r"(a[1]), "r"(a[2]), "r"(a[3]), "r"(b[0]), "r"(b[1]));
}

// ---------------------------------------------------------------------------
// Kernel A: QKV projection via mma.sync tf32 + RoPE epilogue.
// grid (64, 3): x = M-tile (128 rows), y selects {Q,K,V}. 256 threads = 8 warps
// in a 4(M) x 2(N) grid; warp tile 32x64 via m16n8k8 (2 m-tiles x 8 n-tiles).
// K-chunks of 32. As[128][36] (tf32 bits, load-conflict-free), Bs[32][136].
// ---------------------------------------------------------------------------
__global__ __launch_bounds__(256) void qkv_mma(
    const float* __restrict__ x,  const float* __restrict__ Wq,
    const float* __restrict__ Wk, const float* __restrict__ Wv,
    const float* __restrict__ rc, const float* __restrict__ rs)
{
    __shared__ uint32_t As[128][36];   // [m][k], pad 36: frag loads bank 4*gid+tig
    __shared__ uint32_t Bs[32][136];   // [k][n], pad 136: frag loads bank 8*tig+gid

    const int which = blockIdx.y;
    const float* W = (which == 0) ? Wq : (which == 1) ? Wk : Wv;
    float* out     = (which == 0) ? g_Q : (which == 1) ? g_K : g_V;
    const int m0   = blockIdx.x * 128;

    const int tid  = threadIdx.x;
    const int wid  = tid >> 5, lane = tid & 31;
    const int gid  = lane >> 2, tig = lane & 3;
    const int wm   = (wid >> 1) * 32;     // warp row base
    const int wn   = (wid & 1) * 64;      // warp col base

    float acc[2][8][4];
#pragma unroll
    for (int mt = 0; mt < 2; mt++)
#pragma unroll
        for (int nt = 0; nt < 8; nt++)
#pragma unroll
            for (int q = 0; q < 4; q++) acc[mt][nt][q] = 0.f;

    for (int c = 0; c < 64; c++) {
        const float* xs = x + (size_t)m0 * EMB_ + c * 32;
        const float* ws = W + (size_t)(c * 32) * HD_;
        // A fill: 128 x 32, float4 reads, tf32-convert, vector store
#pragma unroll
        for (int it = 0; it < 4; it++) {
            int idx = it * 256 + tid;
            int m = idx >> 3, kk = (idx & 7) << 2;
            float4 v = *(const float4*)(xs + (size_t)m * EMB_ + kk);
            uint4 u = make_uint4(to_tf32_bits(v.x), to_tf32_bits(v.y),
                                 to_tf32_bits(v.z), to_tf32_bits(v.w));
            *(uint4*)&As[m][kk] = u;
        }
        // B fill: 32 x 128 direct copy (W already [k][n]); conflict-free
#pragma unroll
        for (int it = 0; it < 4; it++) {
            int idx = it * 256 + tid;
            int kk = idx >> 5, n = (idx & 31) << 2;
            float4 v = *(const float4*)(ws + (size_t)kk * HD_ + n);
            uint4 u = make_uint4(to_tf32_bits(v.x), to_tf32_bits(v.y),
                                 to_tf32_bits(v.z), to_tf32_bits(v.w));
            *(uint4*)&Bs[kk][n] = u;
        }
        __syncthreads();

#pragma unroll
        for (int s = 0; s < 4; s++) {          // K=8 slices
            const int kb = s * 8;
            uint32_t a[2][4], b[8][2];
#pragma unroll
            for (int mt = 0; mt < 2; mt++) {
                int mrow = wm + mt * 16 + gid;
                a[mt][0] = As[mrow][kb + tig];
                a[mt][1] = As[mrow + 8][kb + tig];
                a[mt][2] = As[mrow][kb + tig + 4];
                a[mt][3] = As[mrow + 8][kb + tig + 4];
            }
#pragma unroll
            for (int nt = 0; nt < 8; nt++) {
                int ncol = wn + nt * 8 + gid;
                b[nt][0] = Bs[kb + tig][ncol];
                b[nt][1] = Bs[kb + tig + 4][ncol];
            }
#pragma unroll
            for (int mt = 0; mt < 2; mt++)
#pragma unroll
                for (int nt = 0; nt < 8; nt++)
                    mma_tf32(acc[mt][nt], a[mt], b[nt]);
        }
        __syncthreads();
    }

    // Epilogue: C frag (c0,c1) = (row gid, cols 2tig, 2tig+1) -> RoPE pair!
#pragma unroll
    for (int mt = 0; mt < 2; mt++) {
#pragma unroll
        for (int half = 0; half < 2; half++) {    // c0/c1 then c2/c3 (row+8)
            int row = m0 + wm + mt * 16 + gid + half * 8;
            int t = row & (T_ - 1);
#pragma unroll
            for (int nt = 0; nt < 8; nt++) {
                int col = wn + nt * 8 + tig * 2;
                float re = acc[mt][nt][half * 2];
                float im = acc[mt][nt][half * 2 + 1];
                if (which < 2) {
                    float co = rc[t * HALF_ + (col >> 1)];
                    float si = rs[t * HALF_ + (col >> 1)];
                    float nre = re * co - im * si;
                    float nim = re * si + im * co;
                    re = nre; im = nim;
                }
                *(float2*)(out + (size_t)row * HD_ + col) = make_float2(re, im);
            }
        }
    }
}

// ---------------------------------------------------------------------------
// Kernel B: causal flash attention, fp32 SIMT, balanced tile pairing.
// grid (32, 4): each CTA does q-tiles {63-x, x} of 32 rows (load balance).
// 256 threads: tx in [0,16) -> 4 S-cols, ty in [0,16) -> 2 rows.
// Register softmax with 16-lane shuffle reductions; thread-local m/l/alpha.
// ---------------------------------------------------------------------------
__global__ __launch_bounds__(256) void attn2(float* __restrict__ out)
{
    extern __shared__ float sm[];
    float4* Qs = (float4*)sm;            // [32][32] f4, swizzle (r&7)
    float4* Ks = Qs + 32 * 32;           // [64][32] f4, swizzle ((r>>2)&7)
    float4* Vs = Ks + 64 * 32;           // [64][32] f4, plain
    float*  Ps = (float*)(Vs + 64 * 32); // [32][65]

    const int tid = threadIdx.x;
    const int tx = tid & 15, ty = tid >> 4;
    const int b = blockIdx.y;
    const float* gQ = g_Q + (size_t)b * T_ * HD_;
    const float* gK = g_K + (size_t)b * T_ * HD_;
    const float* gV = g_V + (size_t)b * T_ * HD_;

    for (int rep = 0; rep < 2; rep++) {
        const int qt = (rep == 0) ? (63 - (int)blockIdx.x) : (int)blockIdx.x;
        const int q0 = qt * 32;

        // Q tile (scaled), swizzled
#pragma unroll
        for (int it = 0; it < 4; it++) {
            int idx = it * 256 + tid;
            int r = idx >> 5, c4 = idx & 31;
            float4 v = *(const float4*)(gQ + (size_t)(q0 + r) * HD_ + c4 * 4);
            v.x *= SCALE_; v.y *= SCALE_; v.z *= SCALE_; v.w *= SCALE_;
            Qs[r * 32 + (c4 ^ (r & 7))] = v;
        }

        float m_[2] = {-1e30f, -1e30f}, l_[2] = {0.f, 0.f};
        float o[2][8];
#pragma unroll
        for (int i = 0; i < 2; i++)
#pragma unroll
            for (int j = 0; j < 8; j++) o[i][j] = 0.f;

        const int nkv = q0 + 32;
        for (int j0 = 0; j0 < nkv; j0 += 64) {
#pragma unroll
            for (int it = 0; it < 8; it++) {
                int idx = it * 256 + tid;
                int r = idx >> 5, c4 = idx & 31;
                Ks[r * 32 + (c4 ^ ((r >> 2) & 7))] =
                    *(const float4*)(gK + (size_t)(j0 + r) * HD_ + c4 * 4);
                Vs[r * 32 + c4] =
                    *(const float4*)(gV + (size_t)(j0 + r) * HD_ + c4 * 4);
            }
            __syncthreads();

            // S = Q K^T
            float s[2][4];
#pragma unroll
            for (int i = 0; i < 2; i++)
#pragma unroll
                for (int c = 0; c < 4; c++) s[i][c] = 0.f;

#pragma unroll 4
            for (int q4 = 0; q4 < 32; q4++) {
                float4 a0 = Qs[(ty * 2 + 0) * 32 + (q4 ^ ((ty * 2 + 0) & 7))];
                float4 a1 = Qs[(ty * 2 + 1) * 32 + (q4 ^ ((ty * 2 + 1) & 7))];
#pragma unroll
                for (int c = 0; c < 4; c++) {
                    float4 bb = Ks[(tx * 4 + c) * 32 + (q4 ^ (tx & 7))];
                    s[0][c] += a0.x * bb.x + a0.y * bb.y + a0.z * bb.z + a0.w * bb.w;
                    s[1][c] += a1.x * bb.x + a1.y * bb.y + a1.z * bb.z + a1.w * bb.w;
                }
            }

            if (j0 + 64 > q0) {       // diagonal tile: causal mask
#pragma unroll
                for (int i = 0; i < 2; i++)
#pragma unroll
                    for (int c = 0; c < 4; c++)
                        if (j0 + tx * 4 + c > q0 + ty * 2 + i) s[i][c] = -1e30f;
            }

            // register softmax (16-lane reductions per row)
            float alpha[2];
#pragma unroll
            for (int i = 0; i < 2; i++) {
                float mr = fmaxf(fmaxf(s[i][0], s[i][1]), fmaxf(s[i][2], s[i][3]));
#pragma unroll
                for (int off = 8; off >= 1; off >>= 1)
                    mr = fmaxf(mr, __shfl_xor_sync(0xffffffffu, mr, off));
                float mn = fmaxf(m_[i], mr);
                alpha[i] = __expf(m_[i] - mn);
                float rsum = 0.f;
#pragma unroll
                for (int c = 0; c < 4; c++) {
                    float p = __expf(s[i][c] - mn);
                    s[i][c] = p;
                    rsum += p;
                }
#pragma unroll
                for (int off = 8; off >= 1; off >>= 1)
                    rsum += __shfl_xor_sync(0xffffffffu, rsum, off);
                l_[i] = l_[i] * alpha[i] + rsum;
                m_[i] = mn;
                float* prow = Ps + (ty * 2 + i) * 65 + tx * 4;
                prow[0] = s[i][0]; prow[1] = s[i][1];
                prow[2] = s[i][2]; prow[3] = s[i][3];
            }
            __syncthreads();

            // O = O*alpha + P @ V
#pragma unroll
            for (int i = 0; i < 2; i++)
#pragma unroll
                for (int j = 0; j < 8; j++) o[i][j] *= alpha[i];

#pragma unroll 4
            for (int kk = 0; kk < 64; kk++) {
                float4 v0 = Vs[kk * 32 + tx];
                float4 v1 = Vs[kk * 32 + 16 + tx];
                float p0 = Ps[(ty * 2 + 0) * 65 + kk];
                float p1 = Ps[(ty * 2 + 1) * 65 + kk];
                o[0][0] += p0 * v0.x; o[0][1] += p0 * v0.y;
                o[0][2] += p0 * v0.z; o[0][3] += p0 * v0.w;
                o[0][4] += p0 * v1.x; o[0][5] += p0 * v1.y;
                o[0][6] += p0 * v1.z; o[0][7] += p0 * v1.w;
                o[1][0] += p1 * v0.x; o[1][1] += p1 * v0.y;
                o[1][2] += p1 * v0.z; o[1][3] += p1 * v0.w;
                o[1][4] += p1 * v1.x; o[1][5] += p1 * v1.y;
                o[1][6] += p1 * v1.z; o[1][7] += p1 * v1.w;
            }
            __syncthreads();
        }

        // finalize + store
#pragma unroll
        for (int i = 0; i < 2; i++) {
            float inv = 1.f / l_[i];
            int row = q0 + ty * 2 + i;
            float* dst = out + ((size_t)b * T_ + row) * HD_;
            *(float4*)(dst + tx * 4) =
                make_float4(o[i][0] * inv, o[i][1] * inv, o[i][2] * inv, o[i][3] * inv);
            *(float4*)(dst + 64 + tx * 4) =
                make_float4(o[i][4] * inv, o[i][5] * inv, o[i][6] * inv, o[i][7] * inv);
        }
    }
}

// ---------------------------------------------------------------------------
extern "C" void kernel_launch(void* const* d_in, const int* in_sizes, int n_in,
                              void* d_out, int out_size) {
    const float* x  = (const float*)d_in[0];
    const float* Wq = (const float*)d_in[1];
    const float* Wk = (const float*)d_in[2];
    const float* Wv = (const float*)d_in[3];
    const float* rc = (const float*)d_in[4];
    const float* rs = (const float*)d_in[5];
    // d_in[6] = mask: causality applied analytically (identical result)
    float* out = (float*)d_out;

    const int smem_attn = (32 * 32 + 64 * 32 + 64 * 32) * 16 + 32 * 65 * 4;  // 90240
    cudaFuncSetAttribute(attn2, cudaFuncAttributeMaxDynamicSharedMemorySize, smem_attn);

    qkv_mma<<<dim3(64, 3), 256>>>(x, Wq, Wk, Wv, rc, rs);
    attn2<<<dim3(32, B_), 256, smem_attn>>>(out);
}

// round 9
// speedup vs baseline: 3.1625x; 1.8255x over previous
#include <cuda_runtime.h>
#include <cstdint>
#include <math.h>

#define B_ 4
#define T_ 2048
#define EMB_ 2048
#define HD_ 128
#define HALF_ 64
#define SCALE_ 0.08838834764831845f   // 1/sqrt(128)

// __device__ scratch (allocation-free rule)
__device__ float g_Q[B_ * T_ * HD_];
__device__ float g_K[B_ * T_ * HD_];
__device__ float g_V[B_ * T_ * HD_];
// split-KV partials: [b][qt][chunk][64 rows][128] + m,l per row
__device__ float g_pO[B_ * 32 * 4 * 64 * HD_];
__device__ float g_pM[B_ * 32 * 4 * 64];
__device__ float g_pL[B_ * 32 * 4 * 64];

__device__ __forceinline__ uint32_t to_tf32_bits(float v) {
    uint32_t r;
    asm("{ .reg .b32 t; cvt.rna.tf32.f32 t, %1; mov.b32 %0, t; }" : "=r"(r) : "f"(v));
    return r;
}

__device__ __forceinline__ void mma_tf32(float* c, const uint32_t* a, const uint32_t* b) {
    asm volatile(
        "mma.sync.aligned.m16n8k8.row.col.f32.tf32.tf32.f32 "
        "{%0,%1,%2,%3}, {%4,%5,%6,%7}, {%8,%9}, {%0,%1,%2,%3};"
        : "+f"(c[0]), "+f"(c[1]), "+f"(c[2]), "+f"(c[3])
        : "r"(a[0]), "r"(a[1]), "r"(a[2]), "r"(a[3]), "r"(b[0]), "r"(b[1]));
}

// ---------------------------------------------------------------------------
// Kernel A: QKV projection via mma.sync tf32, double-buffered smem, RoPE epi.
// grid (64, 3). 256 threads = 8 warps (4M x 2N); warp tile 32x64.
// ---------------------------------------------------------------------------
__global__ __launch_bounds__(256) void qkv_mma(
    const float* __restrict__ x,  const float* __restrict__ Wq,
    const float* __restrict__ Wk, const float* __restrict__ Wv,
    const float* __restrict__ rc, const float* __restrict__ rs)
{
    extern __shared__ uint32_t dyn[];
    uint32_t* As = dyn;            // 2 bufs x [128][36]
    uint32_t* Bs = dyn + 2 * 4608; // 2 bufs x [32][136]

    const int which = blockIdx.y;
    const float* W = (which == 0) ? Wq : (which == 1) ? Wk : Wv;
    float* out     = (which == 0) ? g_Q : (which == 1) ? g_K : g_V;
    const int m0   = blockIdx.x * 128;

    const int tid  = threadIdx.x;
    const int wid  = tid >> 5, lane = tid & 31;
    const int gid  = lane >> 2, tig = lane & 3;
    const int wm   = (wid >> 1) * 32;
    const int wn   = (wid & 1) * 64;

    // per-thread load coords (4 f4 each for A and B)
    const int am[4] = { (0*256+tid) >> 3, (1*256+tid) >> 3, (2*256+tid) >> 3, (3*256+tid) >> 3 };
    const int ak    = (tid & 7) << 2;
    const int bk[4] = { (0*256+tid) >> 5, (1*256+tid) >> 5, (2*256+tid) >> 5, (3*256+tid) >> 5 };
    const int bn    = (tid & 31) << 2;

    float acc[2][8][4];
#pragma unroll
    for (int mt = 0; mt < 2; mt++)
#pragma unroll
        for (int nt = 0; nt < 8; nt++)
#pragma unroll
            for (int q = 0; q < 4; q++) acc[mt][nt][q] = 0.f;

    float4 ra[4], rb[4];
    // preload chunk 0
#pragma unroll
    for (int it = 0; it < 4; it++) {
        ra[it] = *(const float4*)(x + (size_t)(m0 + am[it]) * EMB_ + ak);
        rb[it] = *(const float4*)(W + (size_t)bk[it] * HD_ + bn);
    }
#pragma unroll
    for (int it = 0; it < 4; it++) {
        uint4 ua = make_uint4(to_tf32_bits(ra[it].x), to_tf32_bits(ra[it].y),
                              to_tf32_bits(ra[it].z), to_tf32_bits(ra[it].w));
        *(uint4*)&As[am[it] * 36 + ak] = ua;
        uint4 ub = make_uint4(to_tf32_bits(rb[it].x), to_tf32_bits(rb[it].y),
                              to_tf32_bits(rb[it].z), to_tf32_bits(rb[it].w));
        *(uint4*)&Bs[bk[it] * 136 + bn] = ub;
    }
    __syncthreads();

    for (int c = 0; c < 64; c++) {
        const int d = c & 1;
        if (c < 63) {      // issue next-chunk loads early
            const float* xs = x + (size_t)m0 * EMB_ + (c + 1) * 32;
            const float* ws = W + (size_t)((c + 1) * 32) * HD_;
#pragma unroll
            for (int it = 0; it < 4; it++) {
                ra[it] = *(const float4*)(xs + (size_t)am[it] * EMB_ + ak);
                rb[it] = *(const float4*)(ws + (size_t)bk[it] * HD_ + bn);
            }
        }
        const uint32_t* Ab = As + d * 4608;
        const uint32_t* Bb = Bs + d * 4352;
#pragma unroll
        for (int s = 0; s < 4; s++) {
            const int kb = s * 8;
            uint32_t a[2][4], b[8][2];
#pragma unroll
            for (int mt = 0; mt < 2; mt++) {
                int mrow = wm + mt * 16 + gid;
                a[mt][0] = Ab[mrow * 36 + kb + tig];
                a[mt][1] = Ab[(mrow + 8) * 36 + kb + tig];
                a[mt][2] = Ab[mrow * 36 + kb + tig + 4];
                a[mt][3] = Ab[(mrow + 8) * 36 + kb + tig + 4];
            }
#pragma unroll
            for (int nt = 0; nt < 8; nt++) {
                int ncol = wn + nt * 8 + gid;
                b[nt][0] = Bb[(kb + tig) * 136 + ncol];
                b[nt][1] = Bb[(kb + tig + 4) * 136 + ncol];
            }
#pragma unroll
            for (int mt = 0; mt < 2; mt++)
#pragma unroll
                for (int nt = 0; nt < 8; nt++)
                    mma_tf32(acc[mt][nt], a[mt], b[nt]);
        }
        if (c < 63) {
            uint32_t* An = As + (1 - d) * 4608;
            uint32_t* Bn = Bs + (1 - d) * 4352;
#pragma unroll
            for (int it = 0; it < 4; it++) {
                uint4 ua = make_uint4(to_tf32_bits(ra[it].x), to_tf32_bits(ra[it].y),
                                      to_tf32_bits(ra[it].z), to_tf32_bits(ra[it].w));
                *(uint4*)&An[am[it] * 36 + ak] = ua;
                uint4 ub = make_uint4(to_tf32_bits(rb[it].x), to_tf32_bits(rb[it].y),
                                      to_tf32_bits(rb[it].z), to_tf32_bits(rb[it].w));
                *(uint4*)&Bn[bk[it] * 136 + bn] = ub;
            }
        }
        __syncthreads();
    }

    // Epilogue: RoPE pairs fall out of the C fragment layout.
#pragma unroll
    for (int mt = 0; mt < 2; mt++) {
#pragma unroll
        for (int half = 0; half < 2; half++) {
            int row = m0 + wm + mt * 16 + gid + half * 8;
            int t = row & (T_ - 1);
#pragma unroll
            for (int nt = 0; nt < 8; nt++) {
                int col = wn + nt * 8 + tig * 2;
                float re = acc[mt][nt][half * 2];
                float im = acc[mt][nt][half * 2 + 1];
                if (which < 2) {
                    float co = rc[t * HALF_ + (col >> 1)];
                    float si = rs[t * HALF_ + (col >> 1)];
                    float nre = re * co - im * si;
                    float nim = re * si + im * co;
                    re = nre; im = nim;
                }
                *(float2*)(out + (size_t)row * HD_ + col) = make_float2(re, im);
            }
        }
    }
}

// ---------------------------------------------------------------------------
// Kernel B1: flash attention phase 1 (mma.sync tf32, split-KV chunks of 512).
// grid (80, 4): x = work item (qt, chunk) per batch, y = batch. 128 threads =
// 4 warps; warp w owns q-rows [16w, 16w+16). kv iters of 64.
// Single-chunk q-tiles (qt<8) write final output; others write partials.
// ---------------------------------------------------------------------------
__global__ __launch_bounds__(128) void attn_p1(float* __restrict__ out)
{
    extern __shared__ uint32_t dyn[];
    uint32_t* Qs = dyn;              // [64][132] tf32 bits
    uint32_t* Ks = Qs + 64 * 132;    // [64][132]
    uint32_t* Vs = Ks + 64 * 132;    // [64][136]
    uint32_t* Ps = Vs + 64 * 136;    // [64][68]

    const int tid = threadIdx.x;
    const int w = tid >> 5, lane = tid & 31;
    const int gid = lane >> 2, tig = lane & 3;
    const int b = blockIdx.y;
    const int i = blockIdx.x;

    int qt, c;
    if (i < 8)       { qt = i;                 c = 0; }
    else if (i < 24) { qt = 8 + (i - 8) / 2;   c = (i - 8) % 2; }
    else if (i < 48) { qt = 16 + (i - 24) / 3; c = (i - 24) % 3; }
    else             { qt = 24 + (i - 48) / 4; c = (i - 48) % 4; }
    const int kv_begin = c * 512;
    const int kv_end   = min((qt + 1) * 64, kv_begin + 512);
    const int niter    = (kv_end - kv_begin) >> 6;
    const int nch      = (qt >> 3) + 1;       // ceil((qt+1)/8)

    const float* gQ = g_Q + (size_t)b * T_ * HD_;
    const float* gK = g_K + (size_t)b * T_ * HD_;
    const float* gV = g_V + (size_t)b * T_ * HD_;

    // Load Q tile (scaled, tf32)
#pragma unroll
    for (int it = 0; it < 16; it++) {
        int idx = it * 128 + tid;
        int r = idx >> 5, c4 = idx & 31;
        float4 v = *(const float4*)(gQ + (size_t)(qt * 64 + r) * HD_ + c4 * 4);
        uint4 u = make_uint4(to_tf32_bits(v.x * SCALE_), to_tf32_bits(v.y * SCALE_),
                             to_tf32_bits(v.z * SCALE_), to_tf32_bits(v.w * SCALE_));
        *(uint4*)&Qs[r * 132 + c4 * 4] = u;
    }

    float o[16][4];
#pragma unroll
    for (int nt = 0; nt < 16; nt++)
#pragma unroll
        for (int q = 0; q < 4; q++) o[nt][q] = 0.f;
    float m0 = -1e30f, m1 = -1e30f, l0 = 0.f, l1 = 0.f;

    const int row0g = qt * 64 + w * 16 + gid;     // global q rows of this thread
    const int row1g = row0g + 8;

    for (int itkv = 0; itkv < niter; itkv++) {
        const int kv0 = kv_begin + itkv * 64;
        // load K, V tiles (tf32)
#pragma unroll
        for (int it = 0; it < 16; it++) {
            int idx = it * 128 + tid;
            int r = idx >> 5, c4 = idx & 31;
            float4 kv = *(const float4*)(gK + (size_t)(kv0 + r) * HD_ + c4 * 4);
            *(uint4*)&Ks[r * 132 + c4 * 4] =
                make_uint4(to_tf32_bits(kv.x), to_tf32_bits(kv.y),
                           to_tf32_bits(kv.z), to_tf32_bits(kv.w));
            float4 vv = *(const float4*)(gV + (size_t)(kv0 + r) * HD_ + c4 * 4);
            *(uint4*)&Vs[r * 136 + c4 * 4] =
                make_uint4(to_tf32_bits(vv.x), to_tf32_bits(vv.y),
                           to_tf32_bits(vv.z), to_tf32_bits(vv.w));
        }
        __syncthreads();

        // S = Q K^T : warp computes 16x64
        float s[8][4];
#pragma unroll
        for (int nt = 0; nt < 8; nt++)
#pragma unroll
            for (int q = 0; q < 4; q++) s[nt][q] = 0.f;
#pragma unroll
        for (int ks = 0; ks < 16; ks++) {
            uint32_t a[4];
            const int ar = (w * 16 + gid) * 132 + ks * 8 + tig;
            a[0] = Qs[ar];
            a[1] = Qs[ar + 8 * 132];
            a[2] = Qs[ar + 4];
            a[3] = Qs[ar + 8 * 132 + 4];
#pragma unroll
            for (int nt = 0; nt < 8; nt++) {
                uint32_t bfr[2];
                const int br = (nt * 8 + gid) * 132 + ks * 8 + tig;
                bfr[0] = Ks[br];
                bfr[1] = Ks[br + 4];
                mma_tf32(s[nt], a, bfr);
            }
        }

        // causal mask (only near the diagonal)
        if (kv0 + 63 > qt * 64 + w * 16) {
#pragma unroll
            for (int nt = 0; nt < 8; nt++) {
                int col = kv0 + nt * 8 + 2 * tig;
                if (col > row0g)     s[nt][0] = -1e30f;
                if (col + 1 > row0g) s[nt][1] = -1e30f;
                if (col > row1g)     s[nt][2] = -1e30f;
                if (col + 1 > row1g) s[nt][3] = -1e30f;
            }
        }

        // online softmax in fragments (rows spread over 4 tig lanes)
        float mr0 = -1e30f, mr1 = -1e30f;
#pragma unroll
        for (int nt = 0; nt < 8; nt++) {
            mr0 = fmaxf(mr0, fmaxf(s[nt][0], s[nt][1]));
            mr1 = fmaxf(mr1, fmaxf(s[nt][2], s[nt][3]));
        }
        mr0 = fmaxf(mr0, __shfl_xor_sync(0xffffffffu, mr0, 1));
        mr0 = fmaxf(mr0, __shfl_xor_sync(0xffffffffu, mr0, 2));
        mr1 = fmaxf(mr1, __shfl_xor_sync(0xffffffffu, mr1, 1));
        mr1 = fmaxf(mr1, __shfl_xor_sync(0xffffffffu, mr1, 2));
        float mn0 = fmaxf(m0, mr0), mn1 = fmaxf(m1, mr1);
        float al0 = __expf(m0 - mn0), al1 = __expf(m1 - mn1);
        float sum0 = 0.f, sum1 = 0.f;
#pragma unroll
        for (int nt = 0; nt < 8; nt++) {
            float p0 = __expf(s[nt][0] - mn0);
            float p1 = __expf(s[nt][1] - mn0);
            float p2 = __expf(s[nt][2] - mn1);
            float p3 = __expf(s[nt][3] - mn1);
            sum0 += p0 + p1; sum1 += p2 + p3;
            const int pc = nt * 8 + 2 * tig;
            *(uint2*)&Ps[(w * 16 + gid) * 68 + pc] =
                make_uint2(to_tf32_bits(p0), to_tf32_bits(p1));
            *(uint2*)&Ps[(w * 16 + gid + 8) * 68 + pc] =
                make_uint2(to_tf32_bits(p2), to_tf32_bits(p3));
        }
        sum0 += __shfl_xor_sync(0xffffffffu, sum0, 1);
        sum0 += __shfl_xor_sync(0xffffffffu, sum0, 2);
        sum1 += __shfl_xor_sync(0xffffffffu, sum1, 1);
        sum1 += __shfl_xor_sync(0xffffffffu, sum1, 2);
        l0 = l0 * al0 + sum0;  l1 = l1 * al1 + sum1;
        m0 = mn0;  m1 = mn1;
        __syncwarp();

        // rescale O, then O += P @ V
#pragma unroll
        for (int nt = 0; nt < 16; nt++) {
            o[nt][0] *= al0; o[nt][1] *= al0;
            o[nt][2] *= al1; o[nt][3] *= al1;
        }
#pragma unroll
        for (int ks = 0; ks < 8; ks++) {
            uint32_t a[4];
            const int ar = (w * 16 + gid) * 68 + ks * 8 + tig;
            a[0] = Ps[ar];
            a[1] = Ps[ar + 8 * 68];
            a[2] = Ps[ar + 4];
            a[3] = Ps[ar + 8 * 68 + 4];
#pragma unroll
            for (int nt = 0; nt < 16; nt++) {
                uint32_t bfr[2];
                const int br = (ks * 8 + tig) * 136 + nt * 8 + gid;
                bfr[0] = Vs[br];
                bfr[1] = Vs[br + 4 * 136];
                mma_tf32(o[nt], a, bfr);
            }
        }
        __syncthreads();
    }

    // epilogue
    const int rl0 = w * 16 + gid, rl1 = rl0 + 8;
    if (nch == 1) {
        float inv0 = 1.f / l0, inv1 = 1.f / l1;
        float* dst = out + (size_t)b * T_ * HD_;
#pragma unroll
        for (int nt = 0; nt < 16; nt++) {
            int col = nt * 8 + 2 * tig;
            *(float2*)(dst + (size_t)(qt * 64 + rl0) * HD_ + col) =
                make_float2(o[nt][0] * inv0, o[nt][1] * inv0);
            *(float2*)(dst + (size_t)(qt * 64 + rl1) * HD_ + col) =
                make_float2(o[nt][2] * inv1, o[nt][3] * inv1);
        }
    } else {
        const size_t sb = ((size_t)((b * 32 + qt) * 4 + c)) * 64;
        float* pO = g_pO + sb * HD_;
#pragma unroll
        for (int nt = 0; nt < 16; nt++) {
            int col = nt * 8 + 2 * tig;
            *(float2*)(pO + (size_t)rl0 * HD_ + col) = make_float2(o[nt][0], o[nt][1]);
            *(float2*)(pO + (size_t)rl1 * HD_ + col) = make_float2(o[nt][2], o[nt][3]);
        }
        if (tig == 0) {
            g_pM[sb + rl0] = m0;  g_pL[sb + rl0] = l0;
            g_pM[sb + rl1] = m1;  g_pL[sb + rl1] = l1;
        }
    }
}

// ---------------------------------------------------------------------------
// Kernel B2: combine split-KV partials for qt >= 8. grid (24, 4), 256 threads.
// ---------------------------------------------------------------------------
__global__ __launch_bounds__(256) void attn_p2(float* __restrict__ out)
{
    const int qt = 8 + blockIdx.x;
    const int b  = blockIdx.y;
    const int nch = (qt >> 3) + 1;          // 2..4
    const int tid = threadIdx.x;
    const int r = tid >> 2, q4 = tid & 3;

    const size_t mlb = ((size_t)(b * 32 + qt) * 4) * 64 + r;
    float mv[4], lv[4];
    float M = -1e30f;
    for (int i = 0; i < nch; i++) {
        mv[i] = g_pM[mlb + (size_t)i * 64];
        lv[i] = g_pL[mlb + (size_t)i * 64];
        M = fmaxf(M, mv[i]);
    }
    float L = 0.f, wgt[4];
    for (int i = 0; i < nch; i++) {
        wgt[i] = __expf(mv[i] - M);
        L += wgt[i] * lv[i];
    }
    const float invL = 1.f / L;

    float4 acc[8];
#pragma unroll
    for (int j = 0; j < 8; j++) acc[j] = make_float4(0.f, 0.f, 0.f, 0.f);
    for (int i = 0; i < nch; i++) {
        const float* src = g_pO +
            (((size_t)((b * 32 + qt) * 4 + i)) * 64 + r) * HD_ + q4 * 32;
        float wg = wgt[i];
#pragma unroll
        for (int j = 0; j < 8; j++) {
            float4 v = *(const float4*)(src + j * 4);
            acc[j].x += wg * v.x; acc[j].y += wg * v.y;
            acc[j].z += wg * v.z; acc[j].w += wg * v.w;
        }
    }
    float* dst = out + ((size_t)b * T_ + qt * 64 + r) * HD_ + q4 * 32;
#pragma unroll
    for (int j = 0; j < 8; j++)
        *(float4*)(dst + j * 4) = make_float4(acc[j].x * invL, acc[j].y * invL,
                                              acc[j].z * invL, acc[j].w * invL);
}

// ---------------------------------------------------------------------------
extern "C" void kernel_launch(void* const* d_in, const int* in_sizes, int n_in,
                              void* d_out, int out_size) {
    const float* x  = (const float*)d_in[0];
    const float* Wq = (const float*)d_in[1];
    const float* Wk = (const float*)d_in[2];
    const float* Wv = (const float*)d_in[3];
    const float* rc = (const float*)d_in[4];
    const float* rs = (const float*)d_in[5];
    // d_in[6] = mask: causality applied analytically (identical result)
    float* out = (float*)d_out;

    const int smem_qkv = 2 * (4608 + 4352) * 4;                          // 71680
    const int smem_p1  = (64 * 132 + 64 * 132 + 64 * 136 + 64 * 68) * 4; // 119808
    cudaFuncSetAttribute(qkv_mma, cudaFuncAttributeMaxDynamicSharedMemorySize, smem_qkv);
    cudaFuncSetAttribute(attn_p1, cudaFuncAttributeMaxDynamicSharedMemorySize, smem_p1);

    qkv_mma<<<dim3(64, 3), 256, smem_qkv>>>(x, Wq, Wk, Wv, rc, rs);
    attn_p1<<<dim3(80, B_), 128, smem_p1>>>(out);
    attn_p2<<<dim3(24, B_), 256>>>(out);
}